// round 3
// baseline (speedup 1.0000x reference)
#include <cuda_runtime.h>
#include <math.h>

#define G 8192
#define S 64
#define D 128
#define H 256
#define EPS 0.01f

// Output layout: rep [G*D] | mixture [G*8] | scale [G] | alpha [G] | beta [G]
#define O_REP   0
#define O_MIX   (G * D)
#define O_SCALE (O_MIX + G * 8)
#define O_ALPHA (O_SCALE + G)
#define O_BETA  (O_ALPHA + G)

// ---------------------------------------------------------------------------
// Kernel 1: per-group statistics -> rep.  One warp per group (S=64 contiguous
// rows of 128 floats). Lane l owns dims [4l, 4l+4).
// ---------------------------------------------------------------------------
__global__ __launch_bounds__(256) void stats_kernel(
    const float* __restrict__ x, const float* __restrict__ y,
    const float* __restrict__ ax, const float* __restrict__ ay,
    float* __restrict__ rep)
{
    const int warp = threadIdx.x >> 5;
    const int lane = threadIdx.x & 31;
    const int g = blockIdx.x * 8 + warp;

    const float4* xg = reinterpret_cast<const float4*>(x + (size_t)g * S * D) + lane;
    const float4  a4 = reinterpret_cast<const float4*>(ax + (size_t)g * D)[lane];
    const float   ayv = ay[g];
    const float*  yg = y + (size_t)g * S;

    float sx0 = 0.f, sx1 = 0.f, sx2 = 0.f, sx3 = 0.f;
    float sp0 = 0.f, sp1 = 0.f, sp2 = 0.f, sp3 = 0.f;
    float sxx = 0.f, sy = 0.f;

#pragma unroll 4
    for (int s = 0; s < S; ++s) {
        float4 xv = xg[s * 32];           // 32 float4 per row
        float  yv = __ldg(yg + s);
        float xr0 = xv.x - a4.x;
        float xr1 = xv.y - a4.y;
        float xr2 = xv.z - a4.z;
        float xr3 = xv.w - a4.w;
        float yr  = yv - ayv;
        sx0 += xr0; sx1 += xr1; sx2 += xr2; sx3 += xr3;
        sp0 += xr0 * yr; sp1 += xr1 * yr; sp2 += xr2 * yr; sp3 += xr3 * yr;
        sxx += xr0 * xr0 + xr1 * xr1 + xr2 * xr2 + xr3 * xr3;
        sy  += yr;
    }

    // warp-reduce tot (= sum over all dims of sx) and sxx
    float tot = sx0 + sx1 + sx2 + sx3;
    float sxxT = sxx;
#pragma unroll
    for (int o = 16; o > 0; o >>= 1) {
        tot  += __shfl_xor_sync(0xffffffffu, tot,  o);
        sxxT += __shfl_xor_sync(0xffffffffu, sxxT, o);
    }

    const float nD = (float)(S * D);               // 8192
    const float var = (sxxT - tot * tot / nD) / (nD - 1.f);
    const float inv = 1.f / var;

    const float invn = 1.f / (float)S;             // 1/64
    const float invn1 = 1.f / (float)(S - 1);      // 1/63
    float4 r;
    r.x = (sp0 - sx0 * sy * invn) * invn1 * inv;
    r.y = (sp1 - sx1 * sy * invn) * invn1 * inv;
    r.z = (sp2 - sx2 * sy * invn) * invn1 * inv;
    r.w = (sp3 - sx3 * sy * invn) * invn1 * inv;
    reinterpret_cast<float4*>(rep + (size_t)g * D)[lane] = r;
}

// ---------------------------------------------------------------------------
// Kernel 2: fused MLP head. Block = 256 threads handles 64 rows (groups).
// W1 (128x256) resident in smem; warp w computes rows [8w,8w+8) with an 8x8
// register tile (cols = lane + 32*j). Then h @ W2 via per-lane partials +
// warp shuffle reduction, epilogue on lane 0.
// ---------------------------------------------------------------------------
__device__ __forceinline__ float softplus_f(float v) {
    return fmaxf(v, 0.f) + log1pf(expf(-fabsf(v)));
}

__global__ __launch_bounds__(256, 1) void mlp_kernel(
    const float* __restrict__ rep, const float* __restrict__ W1,
    const float* __restrict__ b1, const float* __restrict__ W2,
    const float* __restrict__ b2, float* __restrict__ out)
{
    extern __shared__ float smem[];
    float* sW1 = smem;             // 128*256 = 32768
    float* sA  = sW1 + 32768;      // 64*128  = 8192
    float* sW2 = sA + 8192;        // 256*10  = 2560
    float* sb1 = sW2 + 2560;       // 256

    const int t = threadIdx.x;
    // cooperative loads
    {
        float4* dst = reinterpret_cast<float4*>(sW1);
        const float4* src = reinterpret_cast<const float4*>(W1);
#pragma unroll
        for (int i = 0; i < 32; ++i) dst[t + i * 256] = src[t + i * 256];
    }
    {
        float4* dst = reinterpret_cast<float4*>(sA);
        const float4* src = reinterpret_cast<const float4*>(rep + (size_t)blockIdx.x * 64 * D);
#pragma unroll
        for (int i = 0; i < 8; ++i) dst[t + i * 256] = src[t + i * 256];
    }
    for (int i = t; i < 2560; i += 256) sW2[i] = W2[i];
    sb1[t] = b1[t];
    __syncthreads();

    const int warp = t >> 5;
    const int lane = t & 31;

    float acc[8][8];
#pragma unroll
    for (int r = 0; r < 8; ++r)
#pragma unroll
        for (int j = 0; j < 8; ++j) acc[r][j] = 0.f;

    const float* Abase = sA + warp * 8 * D;

#pragma unroll 4
    for (int k = 0; k < D; ++k) {
        float a[8], w[8];
#pragma unroll
        for (int r = 0; r < 8; ++r) a[r] = Abase[r * D + k];       // broadcast LDS
#pragma unroll
        for (int j = 0; j < 8; ++j) w[j] = sW1[k * H + lane + 32 * j];
#pragma unroll
        for (int r = 0; r < 8; ++r)
#pragma unroll
            for (int j = 0; j < 8; ++j) acc[r][j] += a[r] * w[j];
    }

    float b1c[8];
#pragma unroll
    for (int j = 0; j < 8; ++j) b1c[j] = sb1[lane + 32 * j];

    // h @ W2 partials: p[r][k] = sum over this lane's 8 columns
    float p[8][10];
#pragma unroll
    for (int r = 0; r < 8; ++r)
#pragma unroll
        for (int k = 0; k < 10; ++k) p[r][k] = 0.f;

#pragma unroll
    for (int j = 0; j < 8; ++j) {
        float w2r[10];
        const float* w2row = sW2 + (lane + 32 * j) * 10;
#pragma unroll
        for (int k = 0; k < 10; ++k) w2r[k] = w2row[k];
#pragma unroll
        for (int r = 0; r < 8; ++r) {
            float hv = tanhf(acc[r][j] + b1c[j]);
#pragma unroll
            for (int k = 0; k < 10; ++k) p[r][k] += hv * w2r[k];
        }
    }

    // warp reduction + epilogue
#pragma unroll
    for (int r = 0; r < 8; ++r) {
#pragma unroll
        for (int k = 0; k < 10; ++k) {
#pragma unroll
            for (int o = 16; o > 0; o >>= 1)
                p[r][k] += __shfl_xor_sync(0xffffffffu, p[r][k], o);
        }
        if (lane == 0) {
            const int g = blockIdx.x * 64 + warp * 8 + r;
            float o0 = p[r][0] + b2[0];
            float o1 = p[r][1] + b2[1];
            float alpha = softplus_f(o0) * (1.f - EPS) + EPS;
            float beta  = softplus_f(o1) * (1.f - EPS) + EPS;

            float lg[8];
            float mx = -3.4e38f;
#pragma unroll
            for (int k = 0; k < 8; ++k) {
                lg[k] = p[r][2 + k] + b2[2 + k];
                mx = fmaxf(mx, lg[k]);
            }
            float se = 0.f;
#pragma unroll
            for (int k = 0; k < 8; ++k) { lg[k] = expf(lg[k] - mx); se += lg[k]; }
            float inv_se = 1.f / se;
#pragma unroll
            for (int k = 0; k < 8; ++k) out[O_MIX + (size_t)g * 8 + k] = lg[k] * inv_se;

            out[O_SCALE + g] = sqrtf(beta / alpha);
            out[O_ALPHA + g] = alpha;
            out[O_BETA  + g] = beta;
        }
    }
}

// ---------------------------------------------------------------------------
extern "C" void kernel_launch(void* const* d_in, const int* in_sizes, int n_in,
                              void* d_out, int out_size)
{
    (void)in_sizes; (void)n_in; (void)out_size;
    // inputs: 0=index(int32), 1=x, 2=y, 3=anchor_x, 4=anchor_y, 5=W1, 6=b1, 7=W2, 8=b2
    const float* x  = (const float*)d_in[1];
    const float* y  = (const float*)d_in[2];
    const float* ax = (const float*)d_in[3];
    const float* ay = (const float*)d_in[4];
    const float* W1 = (const float*)d_in[5];
    const float* b1 = (const float*)d_in[6];
    const float* W2 = (const float*)d_in[7];
    const float* b2 = (const float*)d_in[8];
    float* out = (float*)d_out;

    const int smem_bytes = (32768 + 8192 + 2560 + 256) * 4;
    cudaFuncSetAttribute(mlp_kernel, cudaFuncAttributeMaxDynamicSharedMemorySize, smem_bytes);

    stats_kernel<<<G / 8, 256>>>(x, y, ax, ay, out + O_REP);
    mlp_kernel<<<G / 64, 256, smem_bytes>>>(out + O_REP, W1, b1, W2, b2, out);
}